// round 14
// baseline (speedup 1.0000x reference)
#include <cuda_runtime.h>
#include <cuda_fp16.h>
#include <math.h>
#include <cstdint>

// VectorQuantizer via mma.sync fp16x2-split GEMM (Markidis 4-product),
// cp.async double-buffered W staging, 4 independent accumulator chains.
// inputs [16,4096,64] f32, weight [1024,64] f32.
// Output (f32): [loss(1) | quantized(65536*64) | perplexity(1) | indices(65536)]
// out+1 only 4B-aligned -> scalar stores into out_q.

#define N_TOK   65536
#define DIM     64
#define NCODE   1024
#define TPB     128
#define TOKB    64
#define NBLK    (N_TOK / TOKB)     // 1024
#define CCH     64                 // codes per chunk
#define NCH     (NCODE / CCH)      // 16
#define RSTR    144                // padded smem row stride (bytes)

// smem layout (dynamic):
//  buf1 = X region (reused for W after A-frag load): 0..18432 (X1@0, X2@9216)
//  buf0: 18432..36864
#define OFF_X1   0
#define OFF_X2   9216
#define OFF_BUF0 18432
#define BUF_SPL  9216               // split2 offset within a buffer
#define OFF_SWSQ 36864              // [2][64] floats
#define OFF_SXSQ 37376
#define OFF_SBI  37632
#define OFF_RED  37888
#define OFF_FLAG 38400
#define SMEM_TOTAL 38656

__device__ __align__(16) float g_wnorm[NCODE * DIM];
__device__ float g_wsq[NCODE];
__device__ __align__(16) __half g_w1[NCODE * DIM];
__device__ __align__(16) __half g_w2[NCODE * DIM];
__device__ int g_counts[NCODE];
__device__ float g_partials[NBLK];
__device__ unsigned g_done;

__device__ __forceinline__ uint32_t smem_u32(const void* p) {
    uint32_t a;
    asm("{ .reg .u64 t; cvta.to.shared.u64 t, %1; cvt.u32.u64 %0, t; }" : "=r"(a) : "l"(p));
    return a;
}

#define LDSM_X4(r, addr) \
    asm volatile("ldmatrix.sync.aligned.m8n8.x4.shared.b16 {%0,%1,%2,%3}, [%4];" \
                 : "=r"((r)[0]), "=r"((r)[1]), "=r"((r)[2]), "=r"((r)[3]) : "r"(addr))
#define MMA16816(c, a, b0, b1) \
    asm volatile("mma.sync.aligned.m16n8k16.row.col.f32.f16.f16.f32 " \
                 "{%0,%1,%2,%3}, {%4,%5,%6,%7}, {%8,%9}, {%0,%1,%2,%3};" \
                 : "+f"((c)[0]), "+f"((c)[1]), "+f"((c)[2]), "+f"((c)[3]) \
                 : "r"((a)[0]), "r"((a)[1]), "r"((a)[2]), "r"((a)[3]), "r"(b0), "r"(b1))
#define CP16(dst, src) \
    asm volatile("cp.async.cg.shared.global [%0], [%1], 16;" :: "r"(dst), "l"(src))
#define CP_COMMIT() asm volatile("cp.async.commit_group;" ::: "memory")
#define CP_WAIT1()  asm volatile("cp.async.wait_group 1;" ::: "memory")
#define CP_WAIT0()  asm volatile("cp.async.wait_group 0;" ::: "memory")

// ---------------------------------------------------------------------------
// Kernel 1: prep — zero counters, normalize codebook, fp16x2 split tables.
// ---------------------------------------------------------------------------
__global__ __launch_bounds__(128) void vq_prep(const float* __restrict__ w) {
    int r = blockIdx.x * 128 + threadIdx.x;
    if (r == 0) g_done = 0;
    if (r >= NCODE) return;
    g_counts[r] = 0;
    const float4* src = (const float4*)(w + (size_t)r * DIM);
    float v[DIM];
    float ss = 0.f;
#pragma unroll
    for (int i = 0; i < DIM / 4; i++) {
        float4 q = src[i];
        v[4*i+0] = q.x; v[4*i+1] = q.y; v[4*i+2] = q.z; v[4*i+3] = q.w;
        ss += q.x*q.x + q.y*q.y + q.z*q.z + q.w*q.w;
    }
    float inv = 1.0f / fmaxf(sqrtf(ss), 1e-12f);
    float sq = 0.f;
    float4* dst = (float4*)(g_wnorm + (size_t)r * DIM);
#pragma unroll
    for (int i = 0; i < DIM / 4; i++) {
        float4 q;
        q.x = v[4*i+0] * inv; q.y = v[4*i+1] * inv;
        q.z = v[4*i+2] * inv; q.w = v[4*i+3] * inv;
        sq += q.x*q.x + q.y*q.y + q.z*q.z + q.w*q.w;
        dst[i] = q;
        v[4*i+0] = q.x; v[4*i+1] = q.y; v[4*i+2] = q.z; v[4*i+3] = q.w;
    }
    g_wsq[r] = sq;
#pragma unroll
    for (int d = 0; d < DIM; d++) {
        float e = v[d];
        __half h1 = __float2half_rn(e);
        float r1 = e - __half2float(h1);
        __half h2 = __float2half_rn(r1);
        g_w1[(size_t)r * DIM + d] = h1;
        g_w2[(size_t)r * DIM + d] = h2;
    }
}

// Issue cp.async staging of chunk c0 into buffer at smem offset boff,
// plus the 64 wsq floats into swsq slot. 8+ ops/thread, one commit group.
__device__ __forceinline__ void stage_chunk(uint32_t sb, uint32_t boff,
                                            uint32_t swoff, int c0, int tid) {
    const uint4* s1 = (const uint4*)(g_w1 + (size_t)c0 * DIM);
    const uint4* s2 = (const uint4*)(g_w2 + (size_t)c0 * DIM);
#pragma unroll
    for (int it = 0; it < 4; it++) {          // 512 uint4 per split
        int idx = it * TPB + tid;
        uint32_t doff = (uint32_t)((idx >> 3) * RSTR + (idx & 7) * 16);
        CP16(sb + boff + doff, s1 + idx);
        CP16(sb + boff + BUF_SPL + doff, s2 + idx);
    }
    if (tid < 16)
        CP16(sb + swoff + (uint32_t)tid * 16, (const uint4*)(g_wsq + c0) + tid);
    CP_COMMIT();
}

// ---------------------------------------------------------------------------
// Kernel 2: main — warp-level fp16x2 mma.sync GEMM, 4 chains, cp.async pipe.
// ---------------------------------------------------------------------------
__global__ __launch_bounds__(TPB, 5) void vq_mma(const float* __restrict__ x_in,
                                                 float* __restrict__ out_q,
                                                 float* __restrict__ out_idx,
                                                 float* __restrict__ out_loss,
                                                 float* __restrict__ out_perp) {
    extern __shared__ __align__(16) char smem[];
    const uint32_t sb = smem_u32(smem);
    const int tid  = threadIdx.x;
    const int lane = tid & 31;
    const int wid  = tid >> 5;
    const int T0   = blockIdx.x * TOKB;

    float* sxsq = (float*)(smem + OFF_SXSQ);
    int*   sbi  = (int*)(smem + OFF_SBI);
    float* red  = (float*)(smem + OFF_RED);
    int*   flag = (int*)(smem + OFF_FLAG);

    // ---- prefetch chunk 0 into buf0 (independent of token prep) ----
    stage_chunk(sb, OFF_BUF0, OFF_SWSQ, 0, tid);

    // ---- token prep: threads 0..63 normalize one token, fp16x2 split ----
    if (tid < TOKB) {
        const float4* a4 = (const float4*)(x_in + (size_t)(T0 + tid) * DIM);
        float v[DIM];
        float ss = 0.f;
#pragma unroll
        for (int i = 0; i < DIM / 4; i++) {
            float4 q = a4[i];
            v[4*i+0] = q.x; v[4*i+1] = q.y; v[4*i+2] = q.z; v[4*i+3] = q.w;
            ss += q.x*q.x + q.y*q.y + q.z*q.z + q.w*q.w;
        }
        float inv = 1.0f / fmaxf(sqrtf(ss), 1e-12f);
        float xsq = 0.f;
        const uint32_t rowb = (uint32_t)tid * RSTR;
#pragma unroll
        for (int d = 0; d < DIM; d += 2) {
            float e0 = v[d] * inv, e1 = v[d+1] * inv;
            xsq += e0 * e0 + e1 * e1;
            __half a0 = __float2half_rn(e0);
            __half b0 = __float2half_rn(e0 - __half2float(a0));
            __half a1 = __float2half_rn(e1);
            __half b1 = __float2half_rn(e1 - __half2float(a1));
            uint32_t off = rowb + (uint32_t)(d * 2);
            *(uint32_t*)(smem + OFF_X1 + off) =
                (uint32_t)__half_as_ushort(a0) | ((uint32_t)__half_as_ushort(a1) << 16);
            *(uint32_t*)(smem + OFF_X2 + off) =
                (uint32_t)__half_as_ushort(b0) | ((uint32_t)__half_as_ushort(b1) << 16);
        }
        sxsq[tid] = xsq;
    }
    __syncthreads();

    // ---- load whole-kernel A fragments (2 splits x 4 ksteps x 4 regs) ----
    uint32_t A[2][4][4];
    {
        const uint32_t arow = (uint32_t)((wid * 16 + (lane & 15)) * RSTR + ((lane >> 4) & 1) * 16);
#pragma unroll
        for (int k = 0; k < 4; k++) {
            LDSM_X4(A[0][k], sb + OFF_X1 + arow + k * 32);
            LDSM_X4(A[1][k], sb + OFF_X2 + arow + k * 32);
        }
    }
    __syncthreads();   // everyone done reading X region -> reusable as buf1

    // ---- prefetch chunk 1 into buf1 (the X region) ----
    stage_chunk(sb, OFF_X1, OFF_SWSQ + 256, CCH, tid);

    float bdA = INFINITY, bdB = INFINITY;
    int   biA = 0,        biB = 0;

    // B ldmatrix.x4 lane addressing (matrix m = lane>>3):
    //   m0: rows 0-7 k-lo; m1: rows 0-7 k-hi; m2: rows 8-15 k-lo; m3: k-hi.
    const uint32_t brow = (uint32_t)((lane & 7) * RSTR + ((lane >> 3) & 1) * 16
                                     + ((lane >> 4) & 1) * (8 * RSTR));

    for (int ch = 0; ch < NCH; ch++) {
        const int c0 = ch * CCH;
        const uint32_t cur = (ch & 1) ? OFF_X1 : OFF_BUF0;
        const float* swsq = (const float*)(smem + OFF_SWSQ + (ch & 1) * 256);

        if (ch == NCH - 1) CP_WAIT0(); else CP_WAIT1();
        __syncthreads();   // current buffer staged for all threads

#pragma unroll
        for (int nt = 0; nt < 2; nt++) {              // 32 codes per iter
            float cA[4] = {0.f,0.f,0.f,0.f};          // codes +0..7
            float cB[4] = {0.f,0.f,0.f,0.f};          // codes +8..15
            float cC[4] = {0.f,0.f,0.f,0.f};          // codes +16..23
            float cD[4] = {0.f,0.f,0.f,0.f};          // codes +24..31
            const uint32_t bb = (uint32_t)(nt * 32 * RSTR) + brow;
#pragma unroll
            for (int k = 0; k < 4; k++) {
                uint32_t p[4], q[4], r[4], s[4];
                LDSM_X4(p, sb + cur + bb + k * 32);                        // s1 c0-15
                LDSM_X4(r, sb + cur + bb + 16 * RSTR + k * 32);            // s1 c16-31
                LDSM_X4(q, sb + cur + BUF_SPL + bb + k * 32);              // s2 c0-15
                LDSM_X4(s, sb + cur + BUF_SPL + bb + 16 * RSTR + k * 32);  // s2 c16-31
                MMA16816(cA, A[0][k], p[0], p[1]);
                MMA16816(cB, A[0][k], p[2], p[3]);
                MMA16816(cC, A[0][k], r[0], r[1]);
                MMA16816(cD, A[0][k], r[2], r[3]);
                MMA16816(cA, A[0][k], q[0], q[1]);
                MMA16816(cB, A[0][k], q[2], q[3]);
                MMA16816(cC, A[0][k], s[0], s[1]);
                MMA16816(cD, A[0][k], s[2], s[3]);
                MMA16816(cA, A[1][k], p[0], p[1]);
                MMA16816(cB, A[1][k], p[2], p[3]);
                MMA16816(cC, A[1][k], r[0], r[1]);
                MMA16816(cD, A[1][k], r[2], r[3]);
                MMA16816(cA, A[1][k], q[0], q[1]);
                MMA16816(cB, A[1][k], q[2], q[3]);
                MMA16816(cC, A[1][k], s[0], s[1]);
                MMA16816(cD, A[1][k], s[2], s[3]);
            }
            // scores: rows (lane>>2) -> bdA, row+8 -> bdB; ascending code order
            int cb = c0 + nt * 32 + (lane & 3) * 2;
            int lb = nt * 32 + (lane & 3) * 2;
            float* cc[4] = {cA, cB, cC, cD};
#pragma unroll
            for (int g = 0; g < 4; g++) {
                float w0 = swsq[lb + g * 8], w1 = swsq[lb + g * 8 + 1];
                float s0 = fmaf(-2.0f, cc[g][0], w0);
                float s1 = fmaf(-2.0f, cc[g][1], w1);
                float s2 = fmaf(-2.0f, cc[g][2], w0);
                float s3 = fmaf(-2.0f, cc[g][3], w1);
                if (s0 < bdA) { bdA = s0; biA = cb + g * 8; }
                if (s1 < bdA) { bdA = s1; biA = cb + g * 8 + 1; }
                if (s2 < bdB) { bdB = s2; biB = cb + g * 8; }
                if (s3 < bdB) { bdB = s3; biB = cb + g * 8 + 1; }
            }
        }

        __syncthreads();   // all done reading cur before overwriting it
        if (ch + 2 < NCH)
            stage_chunk(sb, cur, OFF_SWSQ + (ch & 1) * 256, (ch + 2) * CCH, tid);
    }

    // ---- cross-lane merge within quad (lex (val,idx) == first-min) ----
#pragma unroll
    for (int d = 1; d <= 2; d <<= 1) {
        float ov = __shfl_xor_sync(0xffffffffu, bdA, d);
        int   oi = __shfl_xor_sync(0xffffffffu, biA, d);
        if (ov < bdA || (ov == bdA && oi < biA)) { bdA = ov; biA = oi; }
        float ov2 = __shfl_xor_sync(0xffffffffu, bdB, d);
        int   oi2 = __shfl_xor_sync(0xffffffffu, biB, d);
        if (ov2 < bdB || (ov2 == bdB && oi2 < biB)) { bdB = ov2; biB = oi2; }
    }

    red[tid] = 0.f;
    __syncthreads();

    if ((lane & 3) == 0) {
        int rowA = lane >> 2;                 // 0..7
        int tA = wid * 16 + rowA;             // block-local token
        int tB = tA + 8;
        sbi[tA] = biA;
        sbi[tB] = biB;
        out_idx[T0 + tA] = (float)biA;
        out_idx[T0 + tB] = (float)biB;
        atomicAdd(&g_counts[biA], 1);
        atomicAdd(&g_counts[biB], 1);
        red[tA] = sxsq[tA] + bdA;             // ||q-x||^2 = xsq + (wsq - 2 dot)
        red[tB] = sxsq[tB] + bdB;
    }
    __syncthreads();

    // ---- coalesced quantized gather/store (out_q only 4B-aligned) ----
#pragma unroll 4
    for (int it = 0; it < (TOKB * DIM) / TPB; it++) {    // 32
        int f = it * TPB + tid;
        int tok = f >> 6, lanec = f & 63;
        out_q[(size_t)T0 * DIM + f] = g_wnorm[(size_t)sbi[tok] * DIM + lanec];
    }

    // ---- deterministic per-block loss partial (red[64..127] are 0) ----
#pragma unroll
    for (int s = TPB / 2; s > 0; s >>= 1) {
        if (tid < s) red[tid] += red[tid + s];
        __syncthreads();
    }
    if (tid == 0) {
        g_partials[blockIdx.x] = red[0];
        __threadfence();
        unsigned v = atomicAdd(&g_done, 1u);
        *flag = (v == NBLK - 1) ? 1 : 0;
    }
    __syncthreads();

    // ---- last block: finalize loss + perplexity (fixed order) ----
    if (*flag) {
        __threadfence();
        float e = 0.f;
#pragma unroll
        for (int j = 0; j < NCODE / TPB; j++) {          // 8
            int c = __ldcg(&g_counts[tid * (NCODE / TPB) + j]);
            float p = (float)c * (1.0f / (float)N_TOK);
            e += p * logf(p + 1e-10f);
        }
        red[tid] = e;
        __syncthreads();
#pragma unroll
        for (int s = TPB / 2; s > 0; s >>= 1) {
            if (tid < s) red[tid] += red[tid + s];
            __syncthreads();
        }
        if (tid == 0) *out_perp = expf(-red[0]);
        __syncthreads();

        float l = 0.f;
#pragma unroll
        for (int j = 0; j < NBLK / TPB; j++)             // 8
            l += __ldcg(&g_partials[tid * (NBLK / TPB) + j]);
        red[tid] = l;
        __syncthreads();
#pragma unroll
        for (int s = TPB / 2; s > 0; s >>= 1) {
            if (tid < s) red[tid] += red[tid + s];
            __syncthreads();
        }
        if (tid == 0)
            *out_loss = 1.25f * (red[0] / (float)((long long)N_TOK * DIM));
    }
}

// ---------------------------------------------------------------------------
extern "C" void kernel_launch(void* const* d_in, const int* in_sizes, int n_in,
                              void* d_out, int out_size) {
    const float* x = (const float*)d_in[0];
    const float* w = (const float*)d_in[1];
    if (n_in >= 2 && in_sizes[0] < in_sizes[1]) {
        x = (const float*)d_in[1];
        w = (const float*)d_in[0];
    }

    float* out = (float*)d_out;
    const long long ND = (long long)N_TOK * DIM;
    float* out_loss = out;
    float* out_q    = out + 1;
    float* out_perp = out + 1 + ND;
    float* out_idx  = out + 2 + ND;

    cudaFuncSetAttribute(vq_mma, cudaFuncAttributeMaxDynamicSharedMemorySize, SMEM_TOTAL);

    vq_prep<<<8, 128>>>(w);
    vq_mma<<<NBLK, TPB, SMEM_TOTAL>>>(x, out_q, out_idx, out_loss, out_perp);
}

// round 15
// speedup vs baseline: 1.4771x; 1.4771x over previous
#include <cuda_runtime.h>
#include <cuda_fp16.h>
#include <math.h>
#include <cstdint>

// VectorQuantizer via mma.sync fp16x2-split GEMM (Markidis 4-product).
// R13 staging (plain LDG/STS, double-barrier per chunk) + R14's verified
// 4-independent-accumulator-chain inner loop.
// Output (f32): [loss(1) | quantized(65536*64) | perplexity(1) | indices(65536)]
// out+1 only 4B-aligned -> scalar stores into out_q.

#define N_TOK   65536
#define DIM     64
#define NCODE   1024
#define TPB     128
#define TOKB    64
#define NBLK    (N_TOK / TOKB)     // 1024
#define CCH     64                 // codes per chunk
#define NCH     (NCODE / CCH)      // 16
#define RSTR    144                // padded smem row stride (bytes)

// smem offsets (dynamic)
#define OFF_X1   0
#define OFF_X2   9216
#define OFF_W1   18432
#define OFF_W2   27648
#define OFF_SWSQ 36864
#define OFF_SXSQ 37120
#define OFF_SBI  37376
#define OFF_RED  37632
#define OFF_FLAG 38144
#define SMEM_TOTAL 38400

__device__ __align__(16) float g_wnorm[NCODE * DIM];
__device__ float g_wsq[NCODE];
__device__ __align__(16) __half g_w1[NCODE * DIM];
__device__ __align__(16) __half g_w2[NCODE * DIM];
__device__ int g_counts[NCODE];
__device__ float g_partials[NBLK];
__device__ unsigned g_done;

__device__ __forceinline__ uint32_t smem_u32(const void* p) {
    uint32_t a;
    asm("{ .reg .u64 t; cvta.to.shared.u64 t, %1; cvt.u32.u64 %0, t; }" : "=r"(a) : "l"(p));
    return a;
}

#define LDSM_X4(r, addr) \
    asm volatile("ldmatrix.sync.aligned.m8n8.x4.shared.b16 {%0,%1,%2,%3}, [%4];" \
                 : "=r"((r)[0]), "=r"((r)[1]), "=r"((r)[2]), "=r"((r)[3]) : "r"(addr))
#define MMA16816(c, a, b0, b1) \
    asm volatile("mma.sync.aligned.m16n8k16.row.col.f32.f16.f16.f32 " \
                 "{%0,%1,%2,%3}, {%4,%5,%6,%7}, {%8,%9}, {%0,%1,%2,%3};" \
                 : "+f"((c)[0]), "+f"((c)[1]), "+f"((c)[2]), "+f"((c)[3]) \
                 : "r"((a)[0]), "r"((a)[1]), "r"((a)[2]), "r"((a)[3]), "r"(b0), "r"(b1))

// ---------------------------------------------------------------------------
// Kernel 1: prep — zero counters, normalize codebook, fp16x2 split tables.
// ---------------------------------------------------------------------------
__global__ __launch_bounds__(128) void vq_prep(const float* __restrict__ w) {
    int r = blockIdx.x * 128 + threadIdx.x;
    if (r == 0) g_done = 0;
    if (r >= NCODE) return;
    g_counts[r] = 0;
    const float4* src = (const float4*)(w + (size_t)r * DIM);
    float v[DIM];
    float ss = 0.f;
#pragma unroll
    for (int i = 0; i < DIM / 4; i++) {
        float4 q = src[i];
        v[4*i+0] = q.x; v[4*i+1] = q.y; v[4*i+2] = q.z; v[4*i+3] = q.w;
        ss += q.x*q.x + q.y*q.y + q.z*q.z + q.w*q.w;
    }
    float inv = 1.0f / fmaxf(sqrtf(ss), 1e-12f);
    float sq = 0.f;
    float4* dst = (float4*)(g_wnorm + (size_t)r * DIM);
#pragma unroll
    for (int i = 0; i < DIM / 4; i++) {
        float4 q;
        q.x = v[4*i+0] * inv; q.y = v[4*i+1] * inv;
        q.z = v[4*i+2] * inv; q.w = v[4*i+3] * inv;
        sq += q.x*q.x + q.y*q.y + q.z*q.z + q.w*q.w;
        dst[i] = q;
        v[4*i+0] = q.x; v[4*i+1] = q.y; v[4*i+2] = q.z; v[4*i+3] = q.w;
    }
    g_wsq[r] = sq;
#pragma unroll
    for (int d = 0; d < DIM; d++) {
        float e = v[d];
        __half h1 = __float2half_rn(e);
        float r1 = e - __half2float(h1);
        __half h2 = __float2half_rn(r1);
        g_w1[(size_t)r * DIM + d] = h1;
        g_w2[(size_t)r * DIM + d] = h2;
    }
}

// ---------------------------------------------------------------------------
// Kernel 2: main — warp-level fp16x2 mma.sync GEMM, 4 chains.
// ---------------------------------------------------------------------------
__global__ __launch_bounds__(TPB) void vq_mma(const float* __restrict__ x_in,
                                              float* __restrict__ out_q,
                                              float* __restrict__ out_idx,
                                              float* __restrict__ out_loss,
                                              float* __restrict__ out_perp) {
    extern __shared__ __align__(16) char smem[];
    const uint32_t sb = smem_u32(smem);
    const int tid  = threadIdx.x;
    const int lane = tid & 31;
    const int wid  = tid >> 5;
    const int T0   = blockIdx.x * TOKB;

    float* swsq = (float*)(smem + OFF_SWSQ);
    float* sxsq = (float*)(smem + OFF_SXSQ);
    int*   sbi  = (int*)(smem + OFF_SBI);
    float* red  = (float*)(smem + OFF_RED);
    int*   flag = (int*)(smem + OFF_FLAG);

    // ---- token prep: threads 0..63 normalize one token, fp16x2 split ----
    if (tid < TOKB) {
        const float4* a4 = (const float4*)(x_in + (size_t)(T0 + tid) * DIM);
        float v[DIM];
        float ss = 0.f;
#pragma unroll
        for (int i = 0; i < DIM / 4; i++) {
            float4 q = a4[i];
            v[4*i+0] = q.x; v[4*i+1] = q.y; v[4*i+2] = q.z; v[4*i+3] = q.w;
            ss += q.x*q.x + q.y*q.y + q.z*q.z + q.w*q.w;
        }
        float inv = 1.0f / fmaxf(sqrtf(ss), 1e-12f);
        float xsq = 0.f;
        const uint32_t rowb = (uint32_t)tid * RSTR;
#pragma unroll
        for (int d = 0; d < DIM; d += 2) {
            float e0 = v[d] * inv, e1 = v[d+1] * inv;
            xsq += e0 * e0 + e1 * e1;
            __half a0 = __float2half_rn(e0);
            __half b0 = __float2half_rn(e0 - __half2float(a0));
            __half a1 = __float2half_rn(e1);
            __half b1 = __float2half_rn(e1 - __half2float(a1));
            uint32_t off = rowb + (uint32_t)(d * 2);
            *(uint32_t*)(smem + OFF_X1 + off) =
                (uint32_t)__half_as_ushort(a0) | ((uint32_t)__half_as_ushort(a1) << 16);
            *(uint32_t*)(smem + OFF_X2 + off) =
                (uint32_t)__half_as_ushort(b0) | ((uint32_t)__half_as_ushort(b1) << 16);
        }
        sxsq[tid] = xsq;
    }
    __syncthreads();

    // ---- load whole-kernel A fragments (2 splits x 4 ksteps x 4 regs) ----
    uint32_t A[2][4][4];
    {
        const uint32_t arow = (uint32_t)((wid * 16 + (lane & 15)) * RSTR + ((lane >> 4) & 1) * 16);
#pragma unroll
        for (int k = 0; k < 4; k++) {
            LDSM_X4(A[0][k], sb + OFF_X1 + arow + k * 32);
            LDSM_X4(A[1][k], sb + OFF_X2 + arow + k * 32);
        }
    }

    float bdA = INFINITY, bdB = INFINITY;
    int   biA = 0,        biB = 0;

    // B ldmatrix.x4 lane addressing (matrix m = lane>>3):
    //   m0: rows 0-7 k-lo; m1: rows 0-7 k-hi; m2: rows 8-15 k-lo; m3: k-hi.
    const uint32_t brow = (uint32_t)((lane & 7) * RSTR + ((lane >> 3) & 1) * 16
                                     + ((lane >> 4) & 1) * (8 * RSTR));

    for (int ch = 0; ch < NCH; ch++) {
        const int c0 = ch * CCH;
        __syncthreads();   // previous chunk's readers done
        {
            const uint4* s1 = (const uint4*)(g_w1 + (size_t)c0 * DIM);
            const uint4* s2 = (const uint4*)(g_w2 + (size_t)c0 * DIM);
#pragma unroll
            for (int it = 0; it < 4; it++) {          // 512 uint4 per split
                int idx = it * TPB + tid;
                uint32_t doff = (uint32_t)((idx >> 3) * RSTR + (idx & 7) * 16);
                *(uint4*)(smem + OFF_W1 + doff) = s1[idx];
                *(uint4*)(smem + OFF_W2 + doff) = s2[idx];
            }
            if (tid < CCH) swsq[tid] = g_wsq[c0 + tid];
        }
        __syncthreads();

#pragma unroll
        for (int nt = 0; nt < 2; nt++) {              // 32 codes per iter
            float cA[4] = {0.f,0.f,0.f,0.f};          // codes +0..7
            float cB[4] = {0.f,0.f,0.f,0.f};          // codes +8..15
            float cC[4] = {0.f,0.f,0.f,0.f};          // codes +16..23
            float cD[4] = {0.f,0.f,0.f,0.f};          // codes +24..31
            const uint32_t bb = (uint32_t)(nt * 32 * RSTR) + brow;
#pragma unroll
            for (int k = 0; k < 4; k++) {
                uint32_t p[4], q[4], r[4], s[4];
                LDSM_X4(p, sb + OFF_W1 + bb + k * 32);                 // s1 c0-15
                LDSM_X4(r, sb + OFF_W1 + bb + 16 * RSTR + k * 32);     // s1 c16-31
                LDSM_X4(q, sb + OFF_W2 + bb + k * 32);                 // s2 c0-15
                LDSM_X4(s, sb + OFF_W2 + bb + 16 * RSTR + k * 32);     // s2 c16-31
                MMA16816(cA, A[0][k], p[0], p[1]);
                MMA16816(cB, A[0][k], p[2], p[3]);
                MMA16816(cC, A[0][k], r[0], r[1]);
                MMA16816(cD, A[0][k], r[2], r[3]);
                MMA16816(cA, A[0][k], q[0], q[1]);
                MMA16816(cB, A[0][k], q[2], q[3]);
                MMA16816(cC, A[0][k], s[0], s[1]);
                MMA16816(cD, A[0][k], s[2], s[3]);
                MMA16816(cA, A[1][k], p[0], p[1]);
                MMA16816(cB, A[1][k], p[2], p[3]);
                MMA16816(cC, A[1][k], r[0], r[1]);
                MMA16816(cD, A[1][k], r[2], r[3]);
                MMA16816(cA, A[1][k], q[0], q[1]);
                MMA16816(cB, A[1][k], q[2], q[3]);
                MMA16816(cC, A[1][k], s[0], s[1]);
                MMA16816(cD, A[1][k], s[2], s[3]);
            }
            // scores: rows (lane>>2) -> bdA, row+8 -> bdB; ascending code order
            int cb = c0 + nt * 32 + (lane & 3) * 2;
            int lb = nt * 32 + (lane & 3) * 2;
            float* cc[4] = {cA, cB, cC, cD};
#pragma unroll
            for (int g = 0; g < 4; g++) {
                float w0 = swsq[lb + g * 8], w1 = swsq[lb + g * 8 + 1];
                float s0 = fmaf(-2.0f, cc[g][0], w0);
                float s1 = fmaf(-2.0f, cc[g][1], w1);
                float s2 = fmaf(-2.0f, cc[g][2], w0);
                float s3 = fmaf(-2.0f, cc[g][3], w1);
                if (s0 < bdA) { bdA = s0; biA = cb + g * 8; }
                if (s1 < bdA) { bdA = s1; biA = cb + g * 8 + 1; }
                if (s2 < bdB) { bdB = s2; biB = cb + g * 8; }
                if (s3 < bdB) { bdB = s3; biB = cb + g * 8 + 1; }
            }
        }
    }

    // ---- cross-lane merge within quad (lex (val,idx) == first-min) ----
#pragma unroll
    for (int d = 1; d <= 2; d <<= 1) {
        float ov = __shfl_xor_sync(0xffffffffu, bdA, d);
        int   oi = __shfl_xor_sync(0xffffffffu, biA, d);
        if (ov < bdA || (ov == bdA && oi < biA)) { bdA = ov; biA = oi; }
        float ov2 = __shfl_xor_sync(0xffffffffu, bdB, d);
        int   oi2 = __shfl_xor_sync(0xffffffffu, biB, d);
        if (ov2 < bdB || (ov2 == bdB && oi2 < biB)) { bdB = ov2; biB = oi2; }
    }

    red[tid] = 0.f;
    __syncthreads();

    if ((lane & 3) == 0) {
        int rowA = lane >> 2;                 // 0..7
        int tA = wid * 16 + rowA;             // block-local token
        int tB = tA + 8;
        sbi[tA] = biA;
        sbi[tB] = biB;
        out_idx[T0 + tA] = (float)biA;
        out_idx[T0 + tB] = (float)biB;
        atomicAdd(&g_counts[biA], 1);
        atomicAdd(&g_counts[biB], 1);
        red[tA] = sxsq[tA] + bdA;             // ||q-x||^2 = xsq + (wsq - 2 dot)
        red[tB] = sxsq[tB] + bdB;
    }
    __syncthreads();

    // ---- coalesced quantized gather/store (out_q only 4B-aligned) ----
#pragma unroll 4
    for (int it = 0; it < (TOKB * DIM) / TPB; it++) {    // 32
        int f = it * TPB + tid;
        int tok = f >> 6, lanec = f & 63;
        out_q[(size_t)T0 * DIM + f] = g_wnorm[(size_t)sbi[tok] * DIM + lanec];
    }

    // ---- deterministic per-block loss partial (red[64..127] are 0) ----
#pragma unroll
    for (int s = TPB / 2; s > 0; s >>= 1) {
        if (tid < s) red[tid] += red[tid + s];
        __syncthreads();
    }
    if (tid == 0) {
        g_partials[blockIdx.x] = red[0];
        __threadfence();
        unsigned v = atomicAdd(&g_done, 1u);
        *flag = (v == NBLK - 1) ? 1 : 0;
    }
    __syncthreads();

    // ---- last block: finalize loss + perplexity (fixed order) ----
    if (*flag) {
        __threadfence();
        float e = 0.f;
#pragma unroll
        for (int j = 0; j < NCODE / TPB; j++) {          // 8
            int c = __ldcg(&g_counts[tid * (NCODE / TPB) + j]);
            float p = (float)c * (1.0f / (float)N_TOK);
            e += p * logf(p + 1e-10f);
        }
        red[tid] = e;
        __syncthreads();
#pragma unroll
        for (int s = TPB / 2; s > 0; s >>= 1) {
            if (tid < s) red[tid] += red[tid + s];
            __syncthreads();
        }
        if (tid == 0) *out_perp = expf(-red[0]);
        __syncthreads();

        float l = 0.f;
#pragma unroll
        for (int j = 0; j < NBLK / TPB; j++)             // 8
            l += __ldcg(&g_partials[tid * (NBLK / TPB) + j]);
        red[tid] = l;
        __syncthreads();
#pragma unroll
        for (int s = TPB / 2; s > 0; s >>= 1) {
            if (tid < s) red[tid] += red[tid + s];
            __syncthreads();
        }
        if (tid == 0)
            *out_loss = 1.25f * (red[0] / (float)((long long)N_TOK * DIM));
    }
}

// ---------------------------------------------------------------------------
extern "C" void kernel_launch(void* const* d_in, const int* in_sizes, int n_in,
                              void* d_out, int out_size) {
    const float* x = (const float*)d_in[0];
    const float* w = (const float*)d_in[1];
    if (n_in >= 2 && in_sizes[0] < in_sizes[1]) {
        x = (const float*)d_in[1];
        w = (const float*)d_in[0];
    }

    float* out = (float*)d_out;
    const long long ND = (long long)N_TOK * DIM;
    float* out_loss = out;
    float* out_q    = out + 1;
    float* out_perp = out + 1 + ND;
    float* out_idx  = out + 2 + ND;

    cudaFuncSetAttribute(vq_mma, cudaFuncAttributeMaxDynamicSharedMemorySize, SMEM_TOTAL);

    vq_prep<<<8, 128>>>(w);
    vq_mma<<<NBLK, TPB, SMEM_TOTAL>>>(x, out_q, out_idx, out_loss, out_perp);
}